// round 3
// baseline (speedup 1.0000x reference)
#include <cuda_runtime.h>
#include <cstdint>

#define NB   512
#define CCH  32
#define LL   1024
#define ASTR (CCH*LL)          // 32768: stride between consecutive n rows
#define BN_EPS 1e-5f

// 64 MB each — scratch activations between layers (allocation-free per rules)
__device__ float g_h1[NB*CCH*LL];
__device__ float g_h2[NB*CCH*LL];

__device__ __forceinline__ uint32_t f2tf32(float f) {
    uint32_t u;
    asm volatile("cvt.rna.tf32.f32 %0, %1;" : "=r"(u) : "f"(f));
    return u;
}

__device__ __forceinline__ void mma_tf32(float* d,
                                         const uint32_t* a, const uint32_t* b) {
    asm volatile(
        "mma.sync.aligned.m16n8k8.row.col.f32.tf32.tf32.f32 "
        "{%0,%1,%2,%3}, {%4,%5,%6,%7}, {%8,%9}, {%0,%1,%2,%3};"
        : "+f"(d[0]), "+f"(d[1]), "+f"(d[2]), "+f"(d[3])
        : "r"(a[0]), "r"(a[1]), "r"(a[2]), "r"(a[3]), "r"(b[0]), "r"(b[1]));
}

__device__ __forceinline__ void cp16(uint32_t saddr, const float* g) {
    asm volatile("cp.async.ca.shared.global [%0], [%1], 16;" :: "r"(saddr), "l"(g));
}

// ---------------------------------------------------------------------------
// GEMM: out[n, c, m] = act( sum_k A[n, c, k] * W[c, layer, m, k] + bias[c, layer, m] )
// CTA tile 128(M=n) x 128(N=m), K-chunk 16, double-buffered cp.async.
// Warps 2(M) x 4(N): warp tile 64x32 via m16n8k8 tf32 mma (4 x 4 frags).
// ---------------------------------------------------------------------------
template <bool RELU>
__global__ __launch_bounds__(256, 2)
void gemm_layer(const float* __restrict__ A, const float* __restrict__ W,
                const float* __restrict__ bias, float* __restrict__ out,
                int layer)
{
    __shared__ float sA[2][128][20];   // [stage][n-row][k] pad->20 (conflict-free)
    __shared__ float sB[2][128][20];   // [stage][m-row][k]

    const int tid  = threadIdx.x;
    const int warp = tid >> 5;
    const int lane = tid & 31;
    const int g    = lane >> 2;        // groupID 0..7
    const int tg   = lane & 3;         // threadID in group 0..3
    const int wm   = warp >> 2;        // 0..1  (M dir)
    const int wn   = warp & 3;         // 0..3  (N dir)

    const int bx = blockIdx.x;         // M tile: n-rows      (4)
    const int by = blockIdx.y;         // N tile: m-cols      (8)
    const int c  = blockIdx.z;         // channel             (32)

    const float* Abase = A + (long)(bx * 128) * ASTR + c * LL;
    const float* Wbase = W + ((long)(c * 3 + layer) * LL + by * 128) * LL;

    // cp.async assignments: 512 float4 per tile per stage, 2 per thread
    const int i0 = tid, i1 = tid + 256;
    const int ar0 = i0 >> 2, aq0 = (i0 & 3) * 4;
    const int ar1 = i1 >> 2, aq1 = (i1 & 3) * 4;

    uint32_t sA0a = (uint32_t)__cvta_generic_to_shared(&sA[0][ar0][aq0]);
    uint32_t sA1a = (uint32_t)__cvta_generic_to_shared(&sA[0][ar1][aq1]);
    uint32_t sB0a = (uint32_t)__cvta_generic_to_shared(&sB[0][ar0][aq0]);
    uint32_t sB1a = (uint32_t)__cvta_generic_to_shared(&sB[0][ar1][aq1]);
    const uint32_t stgoff = (uint32_t)(128 * 20 * sizeof(float));

    float acc[4][4][4];
#pragma unroll
    for (int i = 0; i < 4; i++)
#pragma unroll
        for (int j = 0; j < 4; j++)
#pragma unroll
            for (int r = 0; r < 4; r++) acc[i][j][r] = 0.f;

    auto issue_stage = [&](int st, int k0) {
        uint32_t so = st ? stgoff : 0u;
        cp16(sA0a + so, Abase + (long)ar0 * ASTR + k0 + aq0);
        cp16(sA1a + so, Abase + (long)ar1 * ASTR + k0 + aq1);
        cp16(sB0a + so, Wbase + (long)ar0 * LL + k0 + aq0);
        cp16(sB1a + so, Wbase + (long)ar1 * LL + k0 + aq1);
        asm volatile("cp.async.commit_group;");
    };

    issue_stage(0, 0);

    const int NT = LL / 16;   // 64 k-chunks
    for (int kt = 0; kt < NT; ++kt) {
        if (kt + 1 < NT) {
            issue_stage((kt + 1) & 1, (kt + 1) * 16);
            asm volatile("cp.async.wait_group 1;");
        } else {
            asm volatile("cp.async.wait_group 0;");
        }
        __syncthreads();

        const int st = kt & 1;
#pragma unroll
        for (int ks = 0; ks < 16; ks += 8) {
            uint32_t afr[4][4];
#pragma unroll
            for (int fm = 0; fm < 4; fm++) {
                const int r = wm * 64 + fm * 16 + g;
                afr[fm][0] = f2tf32(sA[st][r    ][ks + tg    ]);
                afr[fm][1] = f2tf32(sA[st][r + 8][ks + tg    ]);
                afr[fm][2] = f2tf32(sA[st][r    ][ks + tg + 4]);
                afr[fm][3] = f2tf32(sA[st][r + 8][ks + tg + 4]);
            }
            uint32_t bfr[4][2];
#pragma unroll
            for (int fn = 0; fn < 4; fn++) {
                const int rn = wn * 32 + fn * 8 + g;
                bfr[fn][0] = f2tf32(sB[st][rn][ks + tg    ]);
                bfr[fn][1] = f2tf32(sB[st][rn][ks + tg + 4]);
            }
#pragma unroll
            for (int fm = 0; fm < 4; fm++)
#pragma unroll
                for (int fn = 0; fn < 4; fn++)
                    mma_tf32(acc[fm][fn], afr[fm], bfr[fn]);
        }
        __syncthreads();
    }

    // Epilogue: bias (+ReLU), float2 stores into (N, C, L) layout
    const float* bp = bias + (long)(c * 3 + layer) * LL + by * 128;
#pragma unroll
    for (int fm = 0; fm < 4; fm++) {
        const int n0 = bx * 128 + wm * 64 + fm * 16 + g;
#pragma unroll
        for (int fn = 0; fn < 4; fn++) {
            const int ml = wn * 32 + fn * 8 + 2 * tg;
            const int mg = by * 128 + ml;
            const float b0 = bp[ml], b1 = bp[ml + 1];
            float v0 = acc[fm][fn][0] + b0;
            float v1 = acc[fm][fn][1] + b1;
            float v2 = acc[fm][fn][2] + b0;
            float v3 = acc[fm][fn][3] + b1;
            if (RELU) {
                v0 = fmaxf(v0, 0.f); v1 = fmaxf(v1, 0.f);
                v2 = fmaxf(v2, 0.f); v3 = fmaxf(v3, 0.f);
            }
            const long o = (long)n0 * ASTR + c * LL + mg;
            *reinterpret_cast<float2*>(out + o)            = make_float2(v0, v1);
            *reinterpret_cast<float2*>(out + o + 8L * ASTR) = make_float2(v2, v3);
        }
    }
}

// ---------------------------------------------------------------------------
// Training-mode BatchNorm over n (biased var), in-place normalize.
// One thread per (c, m) column; two passes (2nd pass is L2-resident).
// ---------------------------------------------------------------------------
__global__ void bn_normalize(float* __restrict__ h,
                             const float* __restrict__ gamma,
                             const float* __restrict__ beta, int j)
{
    const int idx = blockIdx.x * blockDim.x + threadIdx.x;   // 0..32767
    const int c = idx >> 10;
    const int m = idx & 1023;
    float* p = h + (long)c * LL + m;

    float s = 0.f, sq = 0.f;
#pragma unroll 8
    for (int n = 0; n < NB; n++) {
        const float v = p[(long)n * ASTR];
        s += v; sq += v * v;
    }
    const float mean = s * (1.f / NB);
    const float var  = sq * (1.f / NB) - mean * mean;   // biased
    const long  go   = (long)(c * 2 + j) * LL + m;
    const float sc   = gamma[go] * rsqrtf(var + BN_EPS);
    const float sh   = beta[go] - mean * sc;

#pragma unroll 8
    for (int n = 0; n < NB; n++) {
        const long o = (long)n * ASTR;
        p[o] = fmaf(p[o], sc, sh);
    }
}

extern "C" void kernel_launch(void* const* d_in, const int* in_sizes, int n_in,
                              void* d_out, int out_size)
{
    const float* x     = (const float*)d_in[0];
    const float* W     = (const float*)d_in[1];
    const float* b     = (const float*)d_in[2];
    const float* gamma = (const float*)d_in[3];
    const float* beta  = (const float*)d_in[4];
    float* out = (float*)d_out;

    float *h1 = nullptr, *h2 = nullptr;
    cudaGetSymbolAddress((void**)&h1, g_h1);
    cudaGetSymbolAddress((void**)&h2, g_h2);

    dim3 grid(4, 8, 32), blk(256);

    gemm_layer<true ><<<grid, blk>>>(x,  W, b, h1,  0);
    bn_normalize      <<<128,  256>>>(h1, gamma, beta, 0);
    gemm_layer<true ><<<grid, blk>>>(h1, W, b, h2,  1);
    bn_normalize      <<<128,  256>>>(h2, gamma, beta, 1);
    gemm_layer<false><<<grid, blk>>>(h2, W, b, out, 2);
}